// round 15
// baseline (speedup 1.0000x reference)
#include <cuda_runtime.h>
#include <cstdint>

// high_order_input: x[4,8,128,128] f32 -> out[4,8,210,16384] f32
// ht2: 45 pairs c_i*c_j (i<=j); ht3: 165 triples c_i*c_j*c_k (i<=j<=k), matching
// reference tpcm2/tpcm3 order (verified rel_err 3.9e-08 across R1-R14).
//
// R15 = R12 (fully specialized term-major, __stcs streaming stores — the R14
// A/B showed write-back is 9% WORSE, so evict-first is locked in) with one
// change: 4 warps x 32 rows per CTA (block=128) instead of 8x16. Each warp now
// writes 16KB sequential runs per output stream, halving the number of
// interleaved write streams per SM at equal footprint — testing whether DRAM
// row-buffer locality improves with fewer/longer streams. 6720 uniform CTAs,
// plane-major bid order, 12 CTAs/SM.

#define HWDIM 128
#define LPIX  (HWDIM * HWDIM)   // 16384
#define NTERM 210
#define FULLM 0xffffffffu

// constexpr decode of term t -> (i, j, k); k = -1 for order-2 terms.
// Enumeration: t2 = 0..44 (i-major, j>=i); t3 = 45..209 (i-major, j>=i, k>=j).
__host__ __device__ constexpr int dec3(int t, int sel)
{
    if (t < 45) {
        int rem = t, i = 0;
        while (rem >= 9 - i) { rem -= 9 - i; i++; }
        const int j = i + rem;
        return sel == 0 ? i : (sel == 1 ? j : -1);
    }
    int rem = t - 45, i = 0;
    for (;;) {
        const int c = (9 - i) * (10 - i) / 2;
        if (rem < c) break;
        rem -= c; i++;
    }
    int j = i;
    while (rem >= 9 - j) { rem -= 9 - j; j++; }
    const int k = j + rem;
    return sel == 0 ? i : (sel == 1 ? j : k);
}

__device__ __forceinline__ float4 zero4() { return make_float4(0.f, 0.f, 0.f, 0.f); }

__device__ __forceinline__ float4 ldg4(const float* p)
{
    return __ldg(reinterpret_cast<const float4*>(p));
}

// Compile-time horizontal shift of a warp-distributed row (lane L = cols 4L..4L+3).
// C=0 -> cols w-1 (zero pad), C=1 -> centered, C=2 -> cols w+1 (zero pad).
template <int C>
__device__ __forceinline__ float4 hshiftc(float4 v, int lane)
{
    if (C == 1) return v;
    if (C == 0) {
        float pw = __shfl_up_sync(FULLM, v.w, 1);
        return make_float4(lane == 0 ? 0.f : pw, v.x, v.y, v.z);
    }
    float nx = __shfl_down_sync(FULLM, v.x, 1);
    return make_float4(v.y, v.z, v.w, lane == 31 ? 0.f : nx);
}

template <int DR>
__device__ __forceinline__ float4 rpick(float4 rm, float4 rc, float4 rp)
{
    return (DR == 0) ? rm : (DR == 1) ? rc : rp;
}

template <int T>
__device__ __forceinline__ void run_term(const float* __restrict__ xp,
                                         float* __restrict__ op,
                                         int lane, int rowbase)
{
    constexpr int I = dec3(T, 0);
    constexpr int J = dec3(T, 1);
    constexpr int K = dec3(T, 2);
    constexpr bool TRIPLE = (K >= 0);
    constexpr int DI = I / 3, CI = I % 3;
    constexpr int DJ = J / 3, CJ = J % 3;
    constexpr int DK = TRIPLE ? K / 3 : 1;
    constexpr int CK = TRIPLE ? K % 3 : 1;

    const int colb = lane * 4;

    // Rolling 3-row window (zero-padded at plane edges).
    float4 rm = (rowbase > 0) ? ldg4(xp + (rowbase - 1) * HWDIM + colb) : zero4();
    float4 rc = ldg4(xp + rowbase * HWDIM + colb);

    #pragma unroll 4
    for (int it = 0; it < 32; it++) {
        const int h = rowbase + it;
        float4 rp = (h < HWDIM - 1) ? ldg4(xp + (h + 1) * HWDIM + colb) : zero4();

        float4 vi = hshiftc<CI>(rpick<DI>(rm, rc, rp), lane);
        float4 vj = hshiftc<CJ>(rpick<DJ>(rm, rc, rp), lane);

        float4 r;
        r.x = vi.x * vj.x;
        r.y = vi.y * vj.y;
        r.z = vi.z * vj.z;
        r.w = vi.w * vj.w;

        if (TRIPLE) {
            float4 vk = hshiftc<CK>(rpick<DK>(rm, rc, rp), lane);
            r.x *= vk.x;
            r.y *= vk.y;
            r.z *= vk.z;
            r.w *= vk.w;
        }

        __stcs(reinterpret_cast<float4*>(op + h * HWDIM + colb), r);
        rm = rc;
        rc = rp;
    }
}

__global__ __launch_bounds__(128, 12)
void high_order_term_kernel(const float* __restrict__ x, float* __restrict__ out)
{
    const int cta = blockIdx.x;           // plane-major: concurrent CTAs cluster
    const int p   = cta / NTERM;          // writes into a compact output region
    const int t   = cta - p * NTERM;

    const int lane = threadIdx.x & 31;
    const int warp = threadIdx.x >> 5;
    const int rowbase = warp * 32;        // 4 warps x 32 rows = full plane

    const float* __restrict__ xp = x + (size_t)p * LPIX;
    float* __restrict__ op = out + ((size_t)p * NTERM + t) * LPIX;

#define HO_C1(t_) case (t_): run_term<(t_)>(xp, op, lane, rowbase); break;
#define HO_C5(t_)  HO_C1(t_) HO_C1((t_)+1) HO_C1((t_)+2) HO_C1((t_)+3) HO_C1((t_)+4)
#define HO_C25(t_) HO_C5(t_) HO_C5((t_)+5) HO_C5((t_)+10) HO_C5((t_)+15) HO_C5((t_)+20)

    switch (t) {
        HO_C25(0)   HO_C25(25)  HO_C25(50)  HO_C25(75)
        HO_C25(100) HO_C25(125) HO_C25(150) HO_C25(175)
        HO_C5(200)  HO_C5(205)
    }

#undef HO_C25
#undef HO_C5
#undef HO_C1
}

extern "C" void kernel_launch(void* const* d_in, const int* in_sizes, int n_in,
                              void* d_out, int out_size)
{
    const float* x = (const float*)d_in[0];
    float* out = (float*)d_out;
    // tpcm2 (d_in[1]) / tpcm3 (d_in[2]) are compile-time constants for K=3; hardcoded.
    (void)in_sizes; (void)n_in; (void)out_size;

    const int grid = 32 * NTERM;   // 6720 uniform CTAs, plane-major order
    const int block = 128;         // 4 warps x 32 rows
    high_order_term_kernel<<<grid, block>>>(x, out);
}

// round 16
// speedup vs baseline: 2.1284x; 2.1284x over previous
#include <cuda_runtime.h>
#include <cstdint>

// high_order_input: x[4,8,128,128] f32 -> out[4,8,210,16384] f32
// ht2: 45 pairs c_i*c_j (i<=j); ht3: 165 triples c_i*c_j*c_k (i<=j<=k), matching
// reference tpcm2/tpcm3 order (verified rel_err 3.9e-08 across R1-R15).
//
// FINAL (= R12, the measured optimum at 65.632us = ~6.7 TB/s effective write BW,
// 84% of HBM spec — the practical pure-write ceiling for this 440MB output).
// Term-major: 1 CTA = (plane, term), 6720 uniform CTAs, plane-major bid order,
// 8 warps x 16 rows (8KB sequential runs per stream — measured optimum vs 4KB
// and 16KB), term index fully specialized at compile time (all row picks and
// horizontal shifts constant-fold), __stcs evict-first streaming stores
// (measured +9% vs write-back). Swept and rejected: pixel-major (72-80us),
// group-major (67-92us), scalar/64b stores, higher/lower occupancy, longer runs
// (140us), write-back stores (71.7us).

#define HWDIM 128
#define LPIX  (HWDIM * HWDIM)   // 16384
#define NTERM 210
#define FULLM 0xffffffffu

// constexpr decode of term t -> (i, j, k); k = -1 for order-2 terms.
// Enumeration: t2 = 0..44 (i-major, j>=i); t3 = 45..209 (i-major, j>=i, k>=j).
__host__ __device__ constexpr int dec3(int t, int sel)
{
    if (t < 45) {
        int rem = t, i = 0;
        while (rem >= 9 - i) { rem -= 9 - i; i++; }
        const int j = i + rem;
        return sel == 0 ? i : (sel == 1 ? j : -1);
    }
    int rem = t - 45, i = 0;
    for (;;) {
        const int c = (9 - i) * (10 - i) / 2;
        if (rem < c) break;
        rem -= c; i++;
    }
    int j = i;
    while (rem >= 9 - j) { rem -= 9 - j; j++; }
    const int k = j + rem;
    return sel == 0 ? i : (sel == 1 ? j : k);
}

__device__ __forceinline__ float4 zero4() { return make_float4(0.f, 0.f, 0.f, 0.f); }

__device__ __forceinline__ float4 ldg4(const float* p)
{
    return __ldg(reinterpret_cast<const float4*>(p));
}

// Compile-time horizontal shift of a warp-distributed row (lane L = cols 4L..4L+3).
// C=0 -> cols w-1 (zero pad), C=1 -> centered, C=2 -> cols w+1 (zero pad).
template <int C>
__device__ __forceinline__ float4 hshiftc(float4 v, int lane)
{
    if (C == 1) return v;
    if (C == 0) {
        float pw = __shfl_up_sync(FULLM, v.w, 1);
        return make_float4(lane == 0 ? 0.f : pw, v.x, v.y, v.z);
    }
    float nx = __shfl_down_sync(FULLM, v.x, 1);
    return make_float4(v.y, v.z, v.w, lane == 31 ? 0.f : nx);
}

template <int DR>
__device__ __forceinline__ float4 rpick(float4 rm, float4 rc, float4 rp)
{
    return (DR == 0) ? rm : (DR == 1) ? rc : rp;
}

template <int T>
__device__ __forceinline__ void run_term(const float* __restrict__ xp,
                                         float* __restrict__ op,
                                         int lane, int rowbase)
{
    constexpr int I = dec3(T, 0);
    constexpr int J = dec3(T, 1);
    constexpr int K = dec3(T, 2);
    constexpr bool TRIPLE = (K >= 0);
    constexpr int DI = I / 3, CI = I % 3;
    constexpr int DJ = J / 3, CJ = J % 3;
    constexpr int DK = TRIPLE ? K / 3 : 1;
    constexpr int CK = TRIPLE ? K % 3 : 1;

    const int colb = lane * 4;

    // Rolling 3-row window (zero-padded at plane edges).
    float4 rm = (rowbase > 0) ? ldg4(xp + (rowbase - 1) * HWDIM + colb) : zero4();
    float4 rc = ldg4(xp + rowbase * HWDIM + colb);

    #pragma unroll 2
    for (int it = 0; it < 16; it++) {
        const int h = rowbase + it;
        float4 rp = (h < HWDIM - 1) ? ldg4(xp + (h + 1) * HWDIM + colb) : zero4();

        float4 vi = hshiftc<CI>(rpick<DI>(rm, rc, rp), lane);
        float4 vj = hshiftc<CJ>(rpick<DJ>(rm, rc, rp), lane);

        float4 r;
        r.x = vi.x * vj.x;
        r.y = vi.y * vj.y;
        r.z = vi.z * vj.z;
        r.w = vi.w * vj.w;

        if (TRIPLE) {
            float4 vk = hshiftc<CK>(rpick<DK>(rm, rc, rp), lane);
            r.x *= vk.x;
            r.y *= vk.y;
            r.z *= vk.z;
            r.w *= vk.w;
        }

        __stcs(reinterpret_cast<float4*>(op + h * HWDIM + colb), r);
        rm = rc;
        rc = rp;
    }
}

__global__ __launch_bounds__(256, 6)
void high_order_term_kernel(const float* __restrict__ x, float* __restrict__ out)
{
    const int cta = blockIdx.x;           // plane-major: concurrent CTAs cluster
    const int p   = cta / NTERM;          // writes into a compact output region
    const int t   = cta - p * NTERM;

    const int lane = threadIdx.x & 31;
    const int warp = threadIdx.x >> 5;
    const int rowbase = warp * 16;        // 8 warps x 16 rows = full plane

    const float* __restrict__ xp = x + (size_t)p * LPIX;
    float* __restrict__ op = out + ((size_t)p * NTERM + t) * LPIX;

#define HO_C1(t_) case (t_): run_term<(t_)>(xp, op, lane, rowbase); break;
#define HO_C5(t_)  HO_C1(t_) HO_C1((t_)+1) HO_C1((t_)+2) HO_C1((t_)+3) HO_C1((t_)+4)
#define HO_C25(t_) HO_C5(t_) HO_C5((t_)+5) HO_C5((t_)+10) HO_C5((t_)+15) HO_C5((t_)+20)

    switch (t) {
        HO_C25(0)   HO_C25(25)  HO_C25(50)  HO_C25(75)
        HO_C25(100) HO_C25(125) HO_C25(150) HO_C25(175)
        HO_C5(200)  HO_C5(205)
    }

#undef HO_C25
#undef HO_C5
#undef HO_C1
}

extern "C" void kernel_launch(void* const* d_in, const int* in_sizes, int n_in,
                              void* d_out, int out_size)
{
    const float* x = (const float*)d_in[0];
    float* out = (float*)d_out;
    // tpcm2 (d_in[1]) / tpcm3 (d_in[2]) are compile-time constants for K=3; hardcoded.
    (void)in_sizes; (void)n_in; (void)out_size;

    const int grid = 32 * NTERM;   // 6720 uniform CTAs, plane-major order
    const int block = 256;         // 8 warps x 16 rows
    high_order_term_kernel<<<grid, block>>>(x, out);
}

// round 17
// speedup vs baseline: 2.1888x; 1.0284x over previous
#include <cuda_runtime.h>
#include <cstdint>

// high_order_input: x[4,8,128,128] f32 -> out[4,8,210,16384] f32
// ht2: 45 pairs c_i*c_j (i<=j); ht3: 165 triples c_i*c_j*c_k (i<=j<=k), matching
// reference tpcm2/tpcm3 order (verified rel_err 3.9e-08 across R1-R16).
//
// R17: last unmeasured cell of the run-length curve inside the winning
// term-major family. R12 (16-row/8KB runs) = 65.6us; 32-row/16KB = 140.6us;
// 8-row/4KB only ever measured in group-major (confounded). Here: 1 CTA =
// (plane, term, row-half), 13440 uniform CTAs, 8 warps x 8 rows, otherwise
// byte-identical to R12 (full compile-time term specialization, __stcs).
// If flat or worse, R12 is confirmed final at the ~6.7 TB/s write ceiling.

#define HWDIM 128
#define LPIX  (HWDIM * HWDIM)   // 16384
#define NTERM 210
#define FULLM 0xffffffffu

// constexpr decode of term t -> (i, j, k); k = -1 for order-2 terms.
// Enumeration: t2 = 0..44 (i-major, j>=i); t3 = 45..209 (i-major, j>=i, k>=j).
__host__ __device__ constexpr int dec3(int t, int sel)
{
    if (t < 45) {
        int rem = t, i = 0;
        while (rem >= 9 - i) { rem -= 9 - i; i++; }
        const int j = i + rem;
        return sel == 0 ? i : (sel == 1 ? j : -1);
    }
    int rem = t - 45, i = 0;
    for (;;) {
        const int c = (9 - i) * (10 - i) / 2;
        if (rem < c) break;
        rem -= c; i++;
    }
    int j = i;
    while (rem >= 9 - j) { rem -= 9 - j; j++; }
    const int k = j + rem;
    return sel == 0 ? i : (sel == 1 ? j : k);
}

__device__ __forceinline__ float4 zero4() { return make_float4(0.f, 0.f, 0.f, 0.f); }

__device__ __forceinline__ float4 ldg4(const float* p)
{
    return __ldg(reinterpret_cast<const float4*>(p));
}

// Compile-time horizontal shift of a warp-distributed row (lane L = cols 4L..4L+3).
// C=0 -> cols w-1 (zero pad), C=1 -> centered, C=2 -> cols w+1 (zero pad).
template <int C>
__device__ __forceinline__ float4 hshiftc(float4 v, int lane)
{
    if (C == 1) return v;
    if (C == 0) {
        float pw = __shfl_up_sync(FULLM, v.w, 1);
        return make_float4(lane == 0 ? 0.f : pw, v.x, v.y, v.z);
    }
    float nx = __shfl_down_sync(FULLM, v.x, 1);
    return make_float4(v.y, v.z, v.w, lane == 31 ? 0.f : nx);
}

template <int DR>
__device__ __forceinline__ float4 rpick(float4 rm, float4 rc, float4 rp)
{
    return (DR == 0) ? rm : (DR == 1) ? rc : rp;
}

template <int T>
__device__ __forceinline__ void run_term(const float* __restrict__ xp,
                                         float* __restrict__ op,
                                         int lane, int rowbase)
{
    constexpr int I = dec3(T, 0);
    constexpr int J = dec3(T, 1);
    constexpr int K = dec3(T, 2);
    constexpr bool TRIPLE = (K >= 0);
    constexpr int DI = I / 3, CI = I % 3;
    constexpr int DJ = J / 3, CJ = J % 3;
    constexpr int DK = TRIPLE ? K / 3 : 1;
    constexpr int CK = TRIPLE ? K % 3 : 1;

    const int colb = lane * 4;

    // Rolling 3-row window (zero-padded at plane edges).
    float4 rm = (rowbase > 0) ? ldg4(xp + (rowbase - 1) * HWDIM + colb) : zero4();
    float4 rc = ldg4(xp + rowbase * HWDIM + colb);

    #pragma unroll 2
    for (int it = 0; it < 8; it++) {
        const int h = rowbase + it;
        float4 rp = (h < HWDIM - 1) ? ldg4(xp + (h + 1) * HWDIM + colb) : zero4();

        float4 vi = hshiftc<CI>(rpick<DI>(rm, rc, rp), lane);
        float4 vj = hshiftc<CJ>(rpick<DJ>(rm, rc, rp), lane);

        float4 r;
        r.x = vi.x * vj.x;
        r.y = vi.y * vj.y;
        r.z = vi.z * vj.z;
        r.w = vi.w * vj.w;

        if (TRIPLE) {
            float4 vk = hshiftc<CK>(rpick<DK>(rm, rc, rp), lane);
            r.x *= vk.x;
            r.y *= vk.y;
            r.z *= vk.z;
            r.w *= vk.w;
        }

        __stcs(reinterpret_cast<float4*>(op + h * HWDIM + colb), r);
        rm = rc;
        rc = rp;
    }
}

__global__ __launch_bounds__(256, 6)
void high_order_term_kernel(const float* __restrict__ x, float* __restrict__ out)
{
    // bid = (p*NTERM + t)*2 + half: plane-major (concurrent CTAs cluster in a
    // compact output region), each (plane,term) split into two row-halves.
    const int cta  = blockIdx.x;
    const int half = cta & 1;
    const int pt   = cta >> 1;
    const int p    = pt / NTERM;
    const int t    = pt - p * NTERM;

    const int lane = threadIdx.x & 31;
    const int warp = threadIdx.x >> 5;
    const int rowbase = half * 64 + warp * 8;   // 8 warps x 8 rows = 64 rows

    const float* __restrict__ xp = x + (size_t)p * LPIX;
    float* __restrict__ op = out + ((size_t)p * NTERM + t) * LPIX;

#define HO_C1(t_) case (t_): run_term<(t_)>(xp, op, lane, rowbase); break;
#define HO_C5(t_)  HO_C1(t_) HO_C1((t_)+1) HO_C1((t_)+2) HO_C1((t_)+3) HO_C1((t_)+4)
#define HO_C25(t_) HO_C5(t_) HO_C5((t_)+5) HO_C5((t_)+10) HO_C5((t_)+15) HO_C5((t_)+20)

    switch (t) {
        HO_C25(0)   HO_C25(25)  HO_C25(50)  HO_C25(75)
        HO_C25(100) HO_C25(125) HO_C25(150) HO_C25(175)
        HO_C5(200)  HO_C5(205)
    }

#undef HO_C25
#undef HO_C5
#undef HO_C1
}

extern "C" void kernel_launch(void* const* d_in, const int* in_sizes, int n_in,
                              void* d_out, int out_size)
{
    const float* x = (const float*)d_in[0];
    float* out = (float*)d_out;
    // tpcm2 (d_in[1]) / tpcm3 (d_in[2]) are compile-time constants for K=3; hardcoded.
    (void)in_sizes; (void)n_in; (void)out_size;

    const int grid = 32 * NTERM * 2;   // 13440 uniform CTAs, plane-major order
    const int block = 256;             // 8 warps x 8 rows
    high_order_term_kernel<<<grid, block>>>(x, out);
}